// round 9
// baseline (speedup 1.0000x reference)
#include <cuda_runtime.h>
#include <cuda_fp16.h>
#include <stdint.h>

// Problem constants
#define B_N 4
#define S_N 2048
#define D_N 1024
#define H_N 16
#define DK_N 64

#define HEAD_EL (8192u * 1024u)        // B*H*S*DK == M*D
#define IN_EL   (3u * HEAD_EL)
#define W_EL    (4u * 1024u * 1024u)

// fp16 hi/lo scratch (allocation-free: static device globals)
__device__ __half g_inh[IN_EL], g_inl[IN_EL];
__device__ __half g_wh[W_EL],  g_wl[W_EL];
__device__ __half g_qh[HEAD_EL], g_ql[HEAD_EL];
__device__ __half g_kh[HEAD_EL], g_kl[HEAD_EL];
__device__ __half g_vh[HEAD_EL], g_vl[HEAD_EL];
__device__ __half g_ch[HEAD_EL], g_cl[HEAD_EL];

// ===========================================================================
// Helpers (compute_103-portable: ldmatrix / mma.sync / cp.async)
// ===========================================================================
__device__ __forceinline__ uint32_t smem_u32(const void* p) {
    uint32_t a;
    asm("{ .reg .u64 t; cvta.to.shared.u64 t, %1; cvt.u32.u64 %0, t; }"
        : "=r"(a) : "l"(p));
    return a;
}
__device__ __forceinline__ void ldsm_x4(uint32_t* r, uint32_t addr) {
    asm volatile("ldmatrix.sync.aligned.m8n8.x4.shared.b16 {%0,%1,%2,%3}, [%4];"
        : "=r"(r[0]), "=r"(r[1]), "=r"(r[2]), "=r"(r[3]) : "r"(addr));
}
__device__ __forceinline__ void ldsm_x4t(uint32_t* r, uint32_t addr) {
    asm volatile("ldmatrix.sync.aligned.m8n8.x4.trans.shared.b16 {%0,%1,%2,%3}, [%4];"
        : "=r"(r[0]), "=r"(r[1]), "=r"(r[2]), "=r"(r[3]) : "r"(addr));
}
// fp16 x fp16 -> fp32 accumulate
__device__ __forceinline__ void mma_f32(float* d, const uint32_t* a, const uint32_t* b) {
    asm volatile(
        "mma.sync.aligned.m16n8k16.row.col.f32.f16.f16.f32 "
        "{%0,%1,%2,%3}, {%4,%5,%6,%7}, {%8,%9}, {%0,%1,%2,%3};"
        : "+f"(d[0]), "+f"(d[1]), "+f"(d[2]), "+f"(d[3])
        : "r"(a[0]), "r"(a[1]), "r"(a[2]), "r"(a[3]), "r"(b[0]), "r"(b[1]));
}
// fp16 x fp16 -> fp16 accumulate (cross terms)
__device__ __forceinline__ void mma_f16(uint32_t* d, const uint32_t* a, const uint32_t* b) {
    asm volatile(
        "mma.sync.aligned.m16n8k16.row.col.f16.f16.f16.f16 "
        "{%0,%1}, {%2,%3,%4,%5}, {%6,%7}, {%0,%1};"
        : "+r"(d[0]), "+r"(d[1])
        : "r"(a[0]), "r"(a[1]), "r"(a[2]), "r"(a[3]), "r"(b[0]), "r"(b[1]));
}
__device__ __forceinline__ void h16split2(float x, float y, uint32_t& hi, uint32_t& lo) {
    union { __half2 h; uint32_t u; } a, b;
    a.h = __floats2half2_rn(x, y);
    const float2 f = __half22float2(a.h);
    b.h = __floats2half2_rn(x - f.x, y - f.y);
    hi = a.u; lo = b.u;
}
__device__ __forceinline__ float2 h2f2(uint32_t u) {
    union { __half2 h; uint32_t u; } t; t.u = u;
    return __half22float2(t.h);
}
__device__ __forceinline__ void cpa16(uint32_t s, const void* g) {
    asm volatile("cp.async.cg.shared.global [%0], [%1], 16;" :: "r"(s), "l"(g));
}
#define CP_COMMIT() asm volatile("cp.async.commit_group;" ::: "memory")
#define CP_WAIT(n)  asm volatile("cp.async.wait_group %0;" :: "n"(n) : "memory")

// ===========================================================================
// Pre-pass: fp32 -> fp16 hi/lo (fused: 3 inputs / 4 weights per launch)
// ===========================================================================
__global__ __launch_bounds__(256) void convert_in(
    const float* __restrict__ q, const float* __restrict__ k,
    const float* __restrict__ v)
{
    const int z = blockIdx.z;
    const float* src = (z == 0) ? q : (z == 1) ? k : v;
    __half* dh = g_inh + (size_t)z * HEAD_EL;
    __half* dl = g_inl + (size_t)z * HEAD_EL;
    const int i = blockIdx.x * 256 + threadIdx.x;
    const float4 val = ((const float4*)src)[i];
    uint32_t h0, l0, h1, l1;
    h16split2(val.x, val.y, h0, l0);
    h16split2(val.z, val.w, h1, l1);
    ((uint2*)dh)[i] = make_uint2(h0, h1);
    ((uint2*)dl)[i] = make_uint2(l0, l1);
}

__global__ __launch_bounds__(256) void convert_w(
    const float* __restrict__ wq, const float* __restrict__ wk,
    const float* __restrict__ wv, const float* __restrict__ wo)
{
    const int z = blockIdx.z;
    const float* src = (z == 0) ? wq : (z == 1) ? wk : (z == 2) ? wv : wo;
    __half* dh = g_wh + (size_t)z * 1024 * 1024;
    __half* dl = g_wl + (size_t)z * 1024 * 1024;
    const int i = blockIdx.x * 256 + threadIdx.x;
    const float4 val = ((const float4*)src)[i];
    uint32_t h0, l0, h1, l1;
    h16split2(val.x, val.y, h0, l0);
    h16split2(val.z, val.w, h1, l1);
    ((uint2*)dh)[i] = make_uint2(h0, h1);
    ((uint2*)dl)[i] = make_uint2(l0, l1);
}

// ===========================================================================
// GEMM: D = A @ W^T (+bias). CTA 128(M) x 128(N), BK=32, 256 thr
// (8 warps: 4m x 2n, warp tile 32x64), 3-stage cp.async pipeline.
// hi.hi -> fp32 acc ; hi.lo + lo.hi -> shared f16 acc, merged in epilogue.
// Stage: Ah(10240) Al(10240) Bh(10240) Bl(10240) = 40960 B. Row stride 80 B.
// ===========================================================================
#define G_AH 0
#define G_AL 10240
#define G_BH 20480
#define G_BDL 10240             // Bl - Bh
#define G_STAGE 40960
#define SMEM_GEMM (3 * G_STAGE)

__device__ __forceinline__ void gemm_stage_issue(
    uint32_t st, const __half* __restrict__ Ah, const __half* __restrict__ Al,
    const __half* __restrict__ Wh, const __half* __restrict__ Wl, int kt, int tid)
{
    #pragma unroll
    for (int i = 0; i < 8; ++i) {
        const int comp = i >> 1;                 // Ah, Al, Bh, Bl
        const int c = tid + (i & 1) * 256;       // 0..511
        const int row = c >> 2, ch = c & 3;
        const uint32_t d = st + comp * 10240 + row * 80 + ch * 16;
        const __half* src =
            (comp == 0 ? Ah : comp == 1 ? Al : comp == 2 ? Wh : Wl)
            + (size_t)row * 1024 + kt * 32 + ch * 8;
        cpa16(d, src);
    }
}

template <int MODE>
__device__ __forceinline__ void gemm_h_body(
    const __half* __restrict__ Ah, const __half* __restrict__ Al,
    const __half* __restrict__ Wh, const __half* __restrict__ Wl,
    const float* __restrict__ bias, float scale,
    float* __restrict__ outf, __half* __restrict__ outh, __half* __restrict__ outl,
    int bm, int bn)
{
    extern __shared__ char smg[];
    const uint32_t sb = smem_u32(smg);
    const int tid = threadIdx.x;
    const int lane = tid & 31;
    const int w = tid >> 5;
    const int wm = w & 3;               // rows wm*32
    const int wn = w >> 2;              // cols wn*64

    const __half* Agh = Ah + (size_t)bm * 128 * 1024;
    const __half* Agl = Al + (size_t)bm * 128 * 1024;
    const __half* Wgh = Wh + (size_t)bn * 128 * 1024;
    const __half* Wgl = Wl + (size_t)bn * 128 * 1024;

    gemm_stage_issue(sb,               Agh, Agl, Wgh, Wgl, 0, tid); CP_COMMIT();
    gemm_stage_issue(sb + G_STAGE,     Agh, Agl, Wgh, Wgl, 1, tid); CP_COMMIT();
    gemm_stage_issue(sb + 2 * G_STAGE, Agh, Agl, Wgh, Wgl, 2, tid); CP_COMMIT();

    float d[2][8][4];
    uint32_t cx[2][8][2];
    #pragma unroll
    for (int mi = 0; mi < 2; ++mi)
        #pragma unroll
        for (int ni = 0; ni < 8; ++ni) {
            d[mi][ni][0] = d[mi][ni][1] = d[mi][ni][2] = d[mi][ni][3] = 0.0f;
            cx[mi][ni][0] = cx[mi][ni][1] = 0u;
        }

    const int arow = wm * 32 + (lane & 15);
    const int akoff = (lane >> 4) << 3;
    const int brow = wn * 64 + (lane & 7);
    const int bkoff = ((lane >> 3) & 1) << 3;
    const uint32_t losel = (lane & 16) ? G_BDL : 0;

    for (int kt = 0; kt < 32; ++kt) {
        if (kt < 30) { CP_WAIT(2); } else if (kt == 30) { CP_WAIT(1); } else { CP_WAIT(0); }
        __syncthreads();
        const uint32_t st = sb + (uint32_t)(kt % 3) * G_STAGE;
        #pragma unroll
        for (int kk = 0; kk < 32; kk += 16) {
            uint32_t ah[2][4], al[2][4];
            #pragma unroll
            for (int mi = 0; mi < 2; ++mi) {
                const uint32_t ao = st + (arow + mi * 16) * 80 + (kk + akoff) * 2;
                ldsm_x4(ah[mi], ao + G_AH);
                ldsm_x4(al[mi], ao + G_AL);
            }
            #pragma unroll
            for (int ni = 0; ni < 8; ++ni) {
                uint32_t bb[4];   // [0..1]=hi, [2..3]=lo (combined x4 via losel)
                const uint32_t bo = st + G_BH + losel + (brow + ni * 8) * 80 + (kk + bkoff) * 2;
                ldsm_x4(bb, bo);
                #pragma unroll
                for (int mi = 0; mi < 2; ++mi) {
                    mma_f32(d[mi][ni], ah[mi], bb);       // hi*hi  (fp32 acc)
                    mma_f16(cx[mi][ni], ah[mi], bb + 2);  // hi*lo  (f16 acc)
                    mma_f16(cx[mi][ni], al[mi], bb);      // lo*hi  (f16 acc)
                }
            }
        }
        __syncthreads();
        if (kt + 3 < 32) {
            gemm_stage_issue(sb + (uint32_t)(kt % 3) * G_STAGE, Agh, Agl, Wgh, Wgl, kt + 3, tid);
            CP_COMMIT();
        }
    }

    // epilogue: merge cross, add bias, scale, store
    const int r_base = bm * 128 + wm * 32 + (lane >> 2);
    const int c_base = bn * 128 + wn * 64 + 2 * (lane & 3);
    #pragma unroll
    for (int mi = 0; mi < 2; ++mi)
        #pragma unroll
        for (int ni = 0; ni < 8; ++ni) {
            const int col = c_base + ni * 8;
            const float b0 = bias[col], b1 = bias[col + 1];
            const float2 c01 = h2f2(cx[mi][ni][0]);
            const float2 c23 = h2f2(cx[mi][ni][1]);
            const float v0 = (d[mi][ni][0] + c01.x + b0) * scale;
            const float v1 = (d[mi][ni][1] + c01.y + b1) * scale;
            const float v2 = (d[mi][ni][2] + c23.x + b0) * scale;
            const float v3 = (d[mi][ni][3] + c23.y + b1) * scale;
            #pragma unroll
            for (int rr = 0; rr < 2; ++rr) {
                const int row = r_base + mi * 16 + rr * 8;
                const float vx = rr ? v2 : v0;
                const float vy = rr ? v3 : v1;
                if (MODE == 1) {
                    const int bb = row >> 11;
                    const int s = row & (S_N - 1);
                    const int hh = col >> 6;
                    const int dk = col & 63;
                    const size_t idx = (((size_t)(bb * H_N + hh) * S_N + s) * DK_N) + dk;
                    uint32_t h, l;
                    h16split2(vx, vy, h, l);
                    *(uint32_t*)(outh + idx) = h;
                    *(uint32_t*)(outl + idx) = l;
                } else {
                    float2 v; v.x = vx; v.y = vy;
                    *(float2*)(outf + (size_t)row * D_N + col) = v;
                }
            }
        }
}

__global__ __launch_bounds__(256) void qkv_proj_mma(
    const float* __restrict__ bq, const float* __restrict__ bk,
    const float* __restrict__ bv)
{
    const int z = blockIdx.z;
    const float* bias = (z == 0) ? bq : (z == 1) ? bk : bv;
    __half* oh = (z == 0) ? g_qh : (z == 1) ? g_kh : g_vh;
    __half* ol = (z == 0) ? g_ql : (z == 1) ? g_kl : g_vl;
    const float scale = (z == 0) ? 0.125f : 1.0f;
    gemm_h_body<1>(g_inh + (size_t)z * HEAD_EL, g_inl + (size_t)z * HEAD_EL,
                   g_wh + (size_t)z * 1024 * 1024, g_wl + (size_t)z * 1024 * 1024,
                   bias, scale, nullptr, oh, ol, blockIdx.y, blockIdx.x);
}

__global__ __launch_bounds__(256) void oproj_mma(
    const float* __restrict__ bo, float* __restrict__ out)
{
    gemm_h_body<0>(g_ch, g_cl,
                   g_wh + (size_t)3 * 1024 * 1024, g_wl + (size_t)3 * 1024 * 1024,
                   bo, 1.0f, out, nullptr, nullptr, blockIdx.y, blockIdx.x);
}

// ===========================================================================
// Flash attention: CTA = one (b,h) x 128 q-rows, 256 thr (8 warps x 16 rows),
// 64-key tiles, 2-stage cp.async KV pipeline, online softmax.
// hi.hi -> fp32 acc; cross -> f16 acc merged per tile.
// Q persistent in smem (hi/lo). Row stride 144 B.
// ===========================================================================
#define FQ_L 18432               // Q lo offset (Q comp = 128*144)
#define F_ST0 36864
#define F_KDL 9216               // Kl-Kh / Vl-Vh
#define F_VH 18432
#define F_STAGE 36864
#define F_MS (F_ST0 + 2 * F_STAGE)     // 110592
#define SMEM_FLASH (F_MS + 8192)       // 118784

__device__ __forceinline__ void kv_stage_issue(
    uint32_t st, const __half* __restrict__ kh, const __half* __restrict__ kl,
    const __half* __restrict__ vh, const __half* __restrict__ vl, int t, int tid)
{
    #pragma unroll
    for (int i = 0; i < 8; ++i) {
        const int comp = i >> 1;                // Kh,Kl,Vh,Vl
        const int c = tid + (i & 1) * 256;      // 0..511
        const int row = c >> 3, ch = c & 7;
        const uint32_t d = st + comp * 9216 + row * 144 + ch * 16;
        const __half* src =
            (comp == 0 ? kh : comp == 1 ? kl : comp == 2 ? vh : vl)
            + ((size_t)t * 64 + row) * 64 + ch * 8;
        cpa16(d, src);
    }
}

__global__ __launch_bounds__(256)
void flash_mma(const int* __restrict__ mask)
{
    extern __shared__ char smf[];
    const uint32_t sb = smem_u32(smf);
    const int tid = threadIdx.x;
    const int lane = tid & 31;
    const int w = tid >> 5;
    const int bh = blockIdx.y;
    const int q0 = blockIdx.x * 128;
    const int b = bh >> 4;
    const int h = bh & 15;

    const size_t hoff = (size_t)bh * S_N * DK_N;
    const __half* Qh = g_qh + hoff + (size_t)q0 * DK_N;
    const __half* Ql = g_ql + hoff + (size_t)q0 * DK_N;
    const __half* Kh = g_kh + hoff;
    const __half* Kl = g_kl + hoff;
    const __half* Vh = g_vh + hoff;
    const __half* Vl = g_vl + hoff;
    const int* mg = mask + b * S_N;

    // prologue: Q (hi/lo) + mask (group 0), KV stages 0,1 (groups 1,2)
    #pragma unroll
    for (int i = 0; i < 4; ++i) {
        const int c = tid + i * 256;            // 0..1023
        const int row = c >> 3, ch = c & 7;
        const uint32_t d = sb + row * 144 + ch * 16;
        const size_t s = (size_t)row * 64 + ch * 8;
        cpa16(d, Qh + s);
        cpa16(d + FQ_L, Ql + s);
    }
    #pragma unroll
    for (int i = 0; i < 2; ++i) {
        const int c = tid + i * 256;            // 512 chunks = 8192 B
        cpa16(sb + F_MS + c * 16, mg + c * 4);
    }
    CP_COMMIT();
    kv_stage_issue(sb + F_ST0,           Kh, Kl, Vh, Vl, 0, tid); CP_COMMIT();
    kv_stage_issue(sb + F_ST0 + F_STAGE, Kh, Kl, Vh, Vl, 1, tid); CP_COMMIT();

    float o[8][4];
    #pragma unroll
    for (int vi = 0; vi < 8; ++vi)
        #pragma unroll
        for (int q = 0; q < 4; ++q) o[vi][q] = 0.0f;
    float mst[2] = {-1e30f, -1e30f};
    float lst[2] = {0.0f, 0.0f};

    const int qrow = w * 16 + (lane & 15);
    const int qkoff = (lane >> 4) << 3;
    const int brow = lane & 7;
    const int bkoff = ((lane >> 3) & 1) << 3;
    const int vrow = (lane & 7) + bkoff;
    const int c0 = 2 * (lane & 3);
    const uint32_t losel = (lane & 16) ? F_KDL : 0;
    const int* msk = (const int*)(smf + F_MS);

    for (int t = 0; t < 32; ++t) {
        if (t < 31) { CP_WAIT(1); } else { CP_WAIT(0); }
        __syncthreads();
        const uint32_t st = sb + F_ST0 + (uint32_t)(t & 1) * F_STAGE;

        // S = Qs @ K^T  (16 rows x 64 keys per warp)
        float s[8][4];
        uint32_t sc[8][2];
        #pragma unroll
        for (int ni = 0; ni < 8; ++ni) {
            s[ni][0] = s[ni][1] = s[ni][2] = s[ni][3] = 0.0f;
            sc[ni][0] = sc[ni][1] = 0u;
        }

        #pragma unroll
        for (int kc = 0; kc < 4; ++kc) {
            uint32_t qhf[4], qlf[4];
            const uint32_t ao = sb + qrow * 144 + (kc * 16 + qkoff) * 2;
            ldsm_x4(qhf, ao);
            ldsm_x4(qlf, ao + FQ_L);
            #pragma unroll
            for (int ni = 0; ni < 8; ++ni) {
                uint32_t bb[4];
                const uint32_t bo = st + losel + (ni * 8 + brow) * 144 + (kc * 16 + bkoff) * 2;
                ldsm_x4(bb, bo);
                mma_f32(s[ni], qhf, bb);
                mma_f16(sc[ni], qhf, bb + 2);
                mma_f16(sc[ni], qlf, bb);
            }
        }
        // merge cross into fp32 scores
        #pragma unroll
        for (int ni = 0; ni < 8; ++ni) {
            const float2 a = h2f2(sc[ni][0]);
            const float2 bq2 = h2f2(sc[ni][1]);
            s[ni][0] += a.x; s[ni][1] += a.y;
            s[ni][2] += bq2.x; s[ni][3] += bq2.y;
        }

        // mask
        #pragma unroll
        for (int ni = 0; ni < 8; ++ni) {
            if (msk[t * 64 + ni * 8 + c0] == 0)     { s[ni][0] = -1e9f; s[ni][2] = -1e9f; }
            if (msk[t * 64 + ni * 8 + c0 + 1] == 0) { s[ni][1] = -1e9f; s[ni][3] = -1e9f; }
        }

        // online softmax (2 rows per lane)
        #pragma unroll
        for (int rr = 0; rr < 2; ++rr) {
            float mx = -1e30f;
            #pragma unroll
            for (int ni = 0; ni < 8; ++ni)
                mx = fmaxf(mx, fmaxf(s[ni][rr * 2], s[ni][rr * 2 + 1]));
            mx = fmaxf(mx, __shfl_xor_sync(0xffffffffu, mx, 1));
            mx = fmaxf(mx, __shfl_xor_sync(0xffffffffu, mx, 2));
            const float nm = fmaxf(mst[rr], mx);
            const float corr = __expf(mst[rr] - nm);
            float sum = 0.0f;
            #pragma unroll
            for (int ni = 0; ni < 8; ++ni) {
                const float p0 = __expf(s[ni][rr * 2]     - nm);
                const float p1 = __expf(s[ni][rr * 2 + 1] - nm);
                s[ni][rr * 2] = p0; s[ni][rr * 2 + 1] = p1;
                sum += p0 + p1;
            }
            sum += __shfl_xor_sync(0xffffffffu, sum, 1);
            sum += __shfl_xor_sync(0xffffffffu, sum, 2);
            lst[rr] = lst[rr] * corr + sum;
            mst[rr] = nm;
            #pragma unroll
            for (int vi = 0; vi < 8; ++vi) {
                o[vi][rr * 2]     *= corr;
                o[vi][rr * 2 + 1] *= corr;
            }
        }

        // O += P @ V  (cross terms into per-tile f16 acc, merged below)
        uint32_t oc[8][2];
        #pragma unroll
        for (int vi = 0; vi < 8; ++vi) { oc[vi][0] = 0u; oc[vi][1] = 0u; }
        #pragma unroll
        for (int kc = 0; kc < 4; ++kc) {
            uint32_t ph[4], pl[4];
            h16split2(s[2 * kc][0],     s[2 * kc][1],     ph[0], pl[0]);
            h16split2(s[2 * kc][2],     s[2 * kc][3],     ph[1], pl[1]);
            h16split2(s[2 * kc + 1][0], s[2 * kc + 1][1], ph[2], pl[2]);
            h16split2(s[2 * kc + 1][2], s[2 * kc + 1][3], ph[3], pl[3]);
            #pragma unroll
            for (int vi = 0; vi < 8; ++vi) {
                uint32_t vv[4];
                const uint32_t vo = st + F_VH + losel + (kc * 16 + vrow) * 144 + vi * 16;
                ldsm_x4t(vv, vo);
                mma_f32(o[vi], ph, vv);
                mma_f16(oc[vi], ph, vv + 2);
                mma_f16(oc[vi], pl, vv);
            }
        }
        #pragma unroll
        for (int vi = 0; vi < 8; ++vi) {
            const float2 a = h2f2(oc[vi][0]);
            const float2 bq2 = h2f2(oc[vi][1]);
            o[vi][0] += a.x; o[vi][1] += a.y;
            o[vi][2] += bq2.x; o[vi][3] += bq2.y;
        }

        __syncthreads();
        if (t + 2 < 32) {
            kv_stage_issue(sb + F_ST0 + (uint32_t)(t & 1) * F_STAGE, Kh, Kl, Vh, Vl, t + 2, tid);
            CP_COMMIT();
        }
    }

    // epilogue: ctx fp16 hi/lo, flat [b*S+s][D] at col h*64+dk
    #pragma unroll
    for (int rr = 0; rr < 2; ++rr) {
        const float inv = 1.0f / lst[rr];
        const int r = q0 + w * 16 + (lane >> 2) + rr * 8;
        const size_t base = ((size_t)b * S_N + r) * D_N + h * DK_N;
        #pragma unroll
        for (int vi = 0; vi < 8; ++vi) {
            const int dk = vi * 8 + c0;
            uint32_t hh, ll;
            h16split2(o[vi][rr * 2] * inv, o[vi][rr * 2 + 1] * inv, hh, ll);
            *(uint32_t*)(g_ch + base + dk) = hh;
            *(uint32_t*)(g_cl + base + dk) = ll;
        }
    }
}

// ---------------------------------------------------------------------------
extern "C" void kernel_launch(void* const* d_in, const int* in_sizes, int n_in,
                              void* d_out, int out_size)
{
    (void)in_sizes; (void)n_in; (void)out_size;
    const float* query = (const float*)d_in[0];
    const float* key   = (const float*)d_in[1];
    const float* value = (const float*)d_in[2];
    const int*   mask  = (const int*)d_in[3];
    const float* Wq = (const float*)d_in[4];
    const float* bq = (const float*)d_in[5];
    const float* Wk = (const float*)d_in[6];
    const float* bk = (const float*)d_in[7];
    const float* Wv = (const float*)d_in[8];
    const float* bv = (const float*)d_in[9];
    const float* Wo = (const float*)d_in[10];
    const float* bo = (const float*)d_in[11];
    float* out = (float*)d_out;

    cudaFuncSetAttribute(qkv_proj_mma, cudaFuncAttributeMaxDynamicSharedMemorySize, SMEM_GEMM);
    cudaFuncSetAttribute(oproj_mma,    cudaFuncAttributeMaxDynamicSharedMemorySize, SMEM_GEMM);
    cudaFuncSetAttribute(flash_mma,    cudaFuncAttributeMaxDynamicSharedMemorySize, SMEM_FLASH);

    convert_in<<<dim3(HEAD_EL / 4 / 256, 1, 3), 256>>>(query, key, value);
    convert_w<<<dim3(1024 * 1024 / 4 / 256, 1, 4), 256>>>(Wq, Wk, Wv, Wo);

    // GEMM grid: N tiles (1024/128=8) x M tiles (8192/128=64) [x3 for qkv]
    qkv_proj_mma<<<dim3(8, 64, 3), 256, SMEM_GEMM>>>(bq, bk, bv);

    flash_mma<<<dim3(S_N / 128, B_N * H_N), 256, SMEM_FLASH>>>(mask);

    oproj_mma<<<dim3(8, 64), 256, SMEM_GEMM>>>(bo, out);
}

// round 10
// speedup vs baseline: 1.4797x; 1.4797x over previous
#include <cuda_runtime.h>
#include <cuda_fp16.h>
#include <stdint.h>

// Problem constants
#define B_N 4
#define S_N 2048
#define D_N 1024
#define H_N 16
#define DK_N 64

#define HEAD_EL (8192u * 1024u)        // B*H*S*DK == M*D
#define IN_EL   (3u * HEAD_EL)
#define W_EL    (4u * 1024u * 1024u)

// fp16 scratch (allocation-free). A-side: hi only. B-side: hi+lo.
__device__ __half g_inh[IN_EL];                  // q,k,v inputs (A side)
__device__ __half g_wh[W_EL],  g_wl[W_EL];       // weights (B side)
__device__ __half g_qh[HEAD_EL];                 // Q (A side of S)
__device__ __half g_kh[HEAD_EL], g_kl[HEAD_EL];  // K (B side of S)
__device__ __half g_vh[HEAD_EL], g_vl[HEAD_EL];  // V (B side of PV)
__device__ __half g_ch[HEAD_EL];                 // ctx (A side of O proj)

// ===========================================================================
// Helpers (compute_103-portable: ldmatrix / mma.sync / cp.async)
// ===========================================================================
__device__ __forceinline__ uint32_t smem_u32(const void* p) {
    uint32_t a;
    asm("{ .reg .u64 t; cvta.to.shared.u64 t, %1; cvt.u32.u64 %0, t; }"
        : "=r"(a) : "l"(p));
    return a;
}
__device__ __forceinline__ void ldsm_x4(uint32_t* r, uint32_t addr) {
    asm volatile("ldmatrix.sync.aligned.m8n8.x4.shared.b16 {%0,%1,%2,%3}, [%4];"
        : "=r"(r[0]), "=r"(r[1]), "=r"(r[2]), "=r"(r[3]) : "r"(addr));
}
__device__ __forceinline__ void ldsm_x4t(uint32_t* r, uint32_t addr) {
    asm volatile("ldmatrix.sync.aligned.m8n8.x4.trans.shared.b16 {%0,%1,%2,%3}, [%4];"
        : "=r"(r[0]), "=r"(r[1]), "=r"(r[2]), "=r"(r[3]) : "r"(addr));
}
__device__ __forceinline__ void mma_f32(float* d, const uint32_t* a, const uint32_t* b) {
    asm volatile(
        "mma.sync.aligned.m16n8k16.row.col.f32.f16.f16.f32 "
        "{%0,%1,%2,%3}, {%4,%5,%6,%7}, {%8,%9}, {%0,%1,%2,%3};"
        : "+f"(d[0]), "+f"(d[1]), "+f"(d[2]), "+f"(d[3])
        : "r"(a[0]), "r"(a[1]), "r"(a[2]), "r"(a[3]), "r"(b[0]), "r"(b[1]));
}
__device__ __forceinline__ void h16split2(float x, float y, uint32_t& hi, uint32_t& lo) {
    union { __half2 h; uint32_t u; } a, b;
    a.h = __floats2half2_rn(x, y);
    const float2 f = __half22float2(a.h);
    b.h = __floats2half2_rn(x - f.x, y - f.y);
    hi = a.u; lo = b.u;
}
__device__ __forceinline__ uint32_t h2pack(float x, float y) {
    union { __half2 h; uint32_t u; } t;
    t.h = __floats2half2_rn(x, y);
    return t.u;
}
__device__ __forceinline__ void cpa16(uint32_t s, const void* g) {
    asm volatile("cp.async.cg.shared.global [%0], [%1], 16;" :: "r"(s), "l"(g));
}
#define CP_COMMIT() asm volatile("cp.async.commit_group;" ::: "memory")
#define CP_WAIT(n)  asm volatile("cp.async.wait_group %0;" :: "n"(n) : "memory")

// ===========================================================================
// Pre-pass conversions
// ===========================================================================
__global__ __launch_bounds__(256) void convert_in(      // A side: hi only
    const float* __restrict__ q, const float* __restrict__ k,
    const float* __restrict__ v)
{
    const int z = blockIdx.z;
    const float* src = (z == 0) ? q : (z == 1) ? k : v;
    __half* dh = g_inh + (size_t)z * HEAD_EL;
    const int i = blockIdx.x * 256 + threadIdx.x;
    const float4 val = ((const float4*)src)[i];
    ((uint2*)dh)[i] = make_uint2(h2pack(val.x, val.y), h2pack(val.z, val.w));
}

__global__ __launch_bounds__(256) void convert_w(       // B side: hi + lo
    const float* __restrict__ wq, const float* __restrict__ wk,
    const float* __restrict__ wv, const float* __restrict__ wo)
{
    const int z = blockIdx.z;
    const float* src = (z == 0) ? wq : (z == 1) ? wk : (z == 2) ? wv : wo;
    __half* dh = g_wh + (size_t)z * 1024 * 1024;
    __half* dl = g_wl + (size_t)z * 1024 * 1024;
    const int i = blockIdx.x * 256 + threadIdx.x;
    const float4 val = ((const float4*)src)[i];
    uint32_t h0, l0, h1, l1;
    h16split2(val.x, val.y, h0, l0);
    h16split2(val.z, val.w, h1, l1);
    ((uint2*)dh)[i] = make_uint2(h0, h1);
    ((uint2*)dl)[i] = make_uint2(l0, l1);
}

// ===========================================================================
// GEMM: D = A @ W^T (+bias). CTA 128x128, BK=32, 256 thr (8 warps, 32x64),
// 2-term: D = A_hi*(W_hi + W_lo), fp32 acc. 3-stage cp.async pipeline.
// Stage: A(10240) | Bh(10240) | Bl(10240) = 30720 B. Row stride 80 B.
// ===========================================================================
#define G_BH 10240
#define G_BDL 10240             // Bl - Bh
#define G_STAGE 30720
#define SMEM_GEMM (3 * G_STAGE) // 92160

__device__ __forceinline__ void gemm_stage_issue(
    uint32_t st, const __half* __restrict__ Ah,
    const __half* __restrict__ Wh, const __half* __restrict__ Wl, int kt, int tid)
{
    #pragma unroll
    for (int i = 0; i < 2; ++i) {
        const int c = tid + i * 256;             // 0..511
        const int row = c >> 2, ch = c & 3;
        const size_t s = (size_t)row * 1024 + kt * 32 + ch * 8;
        const uint32_t da = st + row * 80 + ch * 16;
        cpa16(da, Ah + s);                        // A hi
        const uint32_t db = st + G_BH + row * 80 + ch * 16;
        cpa16(db, Wh + s);                        // B hi
        cpa16(db + G_BDL, Wl + s);                // B lo
    }
}

template <int MODE>
__device__ __forceinline__ void gemm_h_body(
    const __half* __restrict__ Ah,
    const __half* __restrict__ Wh, const __half* __restrict__ Wl,
    const float* __restrict__ bias, float scale,
    float* __restrict__ outf, __half* __restrict__ outh, __half* __restrict__ outl,
    int bm, int bn)
{
    extern __shared__ char smg[];
    const uint32_t sb = smem_u32(smg);
    const int tid = threadIdx.x;
    const int lane = tid & 31;
    const int w = tid >> 5;
    const int wm = w & 3;               // rows wm*32
    const int wn = w >> 2;              // cols wn*64

    const __half* Agh = Ah + (size_t)bm * 128 * 1024;
    const __half* Wgh = Wh + (size_t)bn * 128 * 1024;
    const __half* Wgl = Wl + (size_t)bn * 128 * 1024;

    gemm_stage_issue(sb,               Agh, Wgh, Wgl, 0, tid); CP_COMMIT();
    gemm_stage_issue(sb + G_STAGE,     Agh, Wgh, Wgl, 1, tid); CP_COMMIT();
    gemm_stage_issue(sb + 2 * G_STAGE, Agh, Wgh, Wgl, 2, tid); CP_COMMIT();

    float d[2][8][4];
    #pragma unroll
    for (int mi = 0; mi < 2; ++mi)
        #pragma unroll
        for (int ni = 0; ni < 8; ++ni)
            #pragma unroll
            for (int q = 0; q < 4; ++q) d[mi][ni][q] = 0.0f;

    const int arow = wm * 32 + (lane & 15);
    const int akoff = (lane >> 4) << 3;
    const int brow = wn * 64 + (lane & 7);
    const int bkoff = ((lane >> 3) & 1) << 3;
    const uint32_t losel = (lane & 16) ? G_BDL : 0;

    for (int kt = 0; kt < 32; ++kt) {
        if (kt < 30) { CP_WAIT(2); } else if (kt == 30) { CP_WAIT(1); } else { CP_WAIT(0); }
        __syncthreads();
        const uint32_t st = sb + (uint32_t)(kt % 3) * G_STAGE;
        #pragma unroll
        for (int kk = 0; kk < 32; kk += 16) {
            uint32_t ah[2][4];
            #pragma unroll
            for (int mi = 0; mi < 2; ++mi) {
                const uint32_t ao = st + (arow + mi * 16) * 80 + (kk + akoff) * 2;
                ldsm_x4(ah[mi], ao);
            }
            #pragma unroll
            for (int ni = 0; ni < 8; ++ni) {
                uint32_t bb[4];   // [0..1]=hi, [2..3]=lo (combined x4 via losel)
                const uint32_t bo = st + G_BH + losel + (brow + ni * 8) * 80 + (kk + bkoff) * 2;
                ldsm_x4(bb, bo);
                #pragma unroll
                for (int mi = 0; mi < 2; ++mi) {
                    mma_f32(d[mi][ni], ah[mi], bb);       // A * B_hi
                    mma_f32(d[mi][ni], ah[mi], bb + 2);   // A * B_lo
                }
            }
        }
        __syncthreads();
        if (kt + 3 < 32) {
            gemm_stage_issue(sb + (uint32_t)(kt % 3) * G_STAGE, Agh, Wgh, Wgl, kt + 3, tid);
            CP_COMMIT();
        }
    }

    // epilogue
    const int r_base = bm * 128 + wm * 32 + (lane >> 2);
    const int c_base = bn * 128 + wn * 64 + 2 * (lane & 3);
    #pragma unroll
    for (int mi = 0; mi < 2; ++mi)
        #pragma unroll
        for (int ni = 0; ni < 8; ++ni) {
            const int col = c_base + ni * 8;
            const float b0 = bias[col], b1 = bias[col + 1];
            #pragma unroll
            for (int rr = 0; rr < 2; ++rr) {
                const int row = r_base + mi * 16 + rr * 8;
                const float vx = (d[mi][ni][rr * 2 + 0] + b0) * scale;
                const float vy = (d[mi][ni][rr * 2 + 1] + b1) * scale;
                if (MODE == 1) {
                    const int bb = row >> 11;
                    const int s = row & (S_N - 1);
                    const int hh = col >> 6;
                    const int dk = col & 63;
                    const size_t idx = (((size_t)(bb * H_N + hh) * S_N + s) * DK_N) + dk;
                    if (outl) {                 // K/V: hi + lo (B side of attention)
                        uint32_t h, l;
                        h16split2(vx, vy, h, l);
                        *(uint32_t*)(outh + idx) = h;
                        *(uint32_t*)(outl + idx) = l;
                    } else {                    // Q: hi only (A side)
                        *(uint32_t*)(outh + idx) = h2pack(vx, vy);
                    }
                } else {
                    float2 v; v.x = vx; v.y = vy;
                    *(float2*)(outf + (size_t)row * D_N + col) = v;
                }
            }
        }
}

__global__ __launch_bounds__(256) void qkv_proj_mma(
    const float* __restrict__ bq, const float* __restrict__ bk,
    const float* __restrict__ bv)
{
    const int z = blockIdx.z;
    const float* bias = (z == 0) ? bq : (z == 1) ? bk : bv;
    __half* oh = (z == 0) ? g_qh : (z == 1) ? g_kh : g_vh;
    __half* ol = (z == 0) ? nullptr : (z == 1) ? g_kl : g_vl;
    const float scale = (z == 0) ? 0.125f : 1.0f;
    gemm_h_body<1>(g_inh + (size_t)z * HEAD_EL,
                   g_wh + (size_t)z * 1024 * 1024, g_wl + (size_t)z * 1024 * 1024,
                   bias, scale, nullptr, oh, ol, blockIdx.y, blockIdx.x);
}

__global__ __launch_bounds__(256) void oproj_mma(
    const float* __restrict__ bo, float* __restrict__ out)
{
    gemm_h_body<0>(g_ch,
                   g_wh + (size_t)3 * 1024 * 1024, g_wl + (size_t)3 * 1024 * 1024,
                   bo, 1.0f, out, nullptr, nullptr, blockIdx.y, blockIdx.x);
}

// ===========================================================================
// Flash attention: CTA = one (b,h) x 256 q-rows, 512 thr (16 warps x 16 rows),
// 64-key tiles, 2-stage cp.async KV pipeline, online softmax.
// 2-term: S = Q*(K_hi+K_lo); O += P*(V_hi+V_lo). Q,P plain fp16.
// Q persistent in smem (hi only, 256x144 B). Stage: Kh|Kl|Vh|Vl (4x9216).
// ===========================================================================
#define F_ST0 36864              // Q hi = 256*144
#define F_KDL 9216               // Kl-Kh / Vl-Vh
#define F_VH 18432
#define F_STAGE 36864
#define F_MS (F_ST0 + 2 * F_STAGE)     // 110592
#define SMEM_FLASH (F_MS + 8192)       // 118784

__device__ __forceinline__ void kv_stage_issue(
    uint32_t st, const __half* __restrict__ kh, const __half* __restrict__ kl,
    const __half* __restrict__ vh, const __half* __restrict__ vl, int t, int tid)
{
    #pragma unroll
    for (int comp = 0; comp < 4; ++comp) {
        const int c = tid & 511;                // 0..511
        const int row = c >> 3, ch = c & 7;
        const uint32_t d = st + comp * 9216 + row * 144 + ch * 16;
        const __half* src =
            (comp == 0 ? kh : comp == 1 ? kl : comp == 2 ? vh : vl)
            + ((size_t)t * 64 + row) * 64 + ch * 8;
        cpa16(d, src);
    }
}

__global__ __launch_bounds__(512, 1)
void flash_mma(const int* __restrict__ mask)
{
    extern __shared__ char smf[];
    const uint32_t sb = smem_u32(smf);
    const int tid = threadIdx.x;
    const int lane = tid & 31;
    const int w = tid >> 5;
    const int bh = blockIdx.y;
    const int q0 = blockIdx.x * 256;
    const int b = bh >> 4;
    const int h = bh & 15;

    const size_t hoff = (size_t)bh * S_N * DK_N;
    const __half* Qh = g_qh + hoff + (size_t)q0 * DK_N;
    const __half* Kh = g_kh + hoff;
    const __half* Kl = g_kl + hoff;
    const __half* Vh = g_vh + hoff;
    const __half* Vl = g_vl + hoff;
    const int* mg = mask + b * S_N;

    // prologue: Q hi + mask (group 0), KV stages 0,1 (groups 1,2)
    #pragma unroll
    for (int i = 0; i < 4; ++i) {
        const int c = tid + i * 512;            // 0..2047
        const int row = c >> 3, ch = c & 7;
        cpa16(sb + row * 144 + ch * 16, Qh + (size_t)row * 64 + ch * 8);
    }
    cpa16(sb + F_MS + tid * 16, mg + tid * 4);  // 512 chunks = 8192 B
    CP_COMMIT();
    kv_stage_issue(sb + F_ST0,           Kh, Kl, Vh, Vl, 0, tid); CP_COMMIT();
    kv_stage_issue(sb + F_ST0 + F_STAGE, Kh, Kl, Vh, Vl, 1, tid); CP_COMMIT();

    float o[8][4];
    #pragma unroll
    for (int vi = 0; vi < 8; ++vi)
        #pragma unroll
        for (int q = 0; q < 4; ++q) o[vi][q] = 0.0f;
    float mst[2] = {-1e30f, -1e30f};
    float lst[2] = {0.0f, 0.0f};

    const int qrow = w * 16 + (lane & 15);
    const int qkoff = (lane >> 4) << 3;
    const int brow = lane & 7;
    const int bkoff = ((lane >> 3) & 1) << 3;
    const int vrow = (lane & 7) + bkoff;
    const int c0 = 2 * (lane & 3);
    const uint32_t losel = (lane & 16) ? F_KDL : 0;
    const int* msk = (const int*)(smf + F_MS);

    for (int t = 0; t < 32; ++t) {
        if (t < 31) { CP_WAIT(1); } else { CP_WAIT(0); }
        __syncthreads();
        const uint32_t st = sb + F_ST0 + (uint32_t)(t & 1) * F_STAGE;

        // S = Q @ (K_hi + K_lo)^T  (16 rows x 64 keys per warp)
        float s[8][4];
        #pragma unroll
        for (int ni = 0; ni < 8; ++ni)
            s[ni][0] = s[ni][1] = s[ni][2] = s[ni][3] = 0.0f;

        #pragma unroll
        for (int kc = 0; kc < 4; ++kc) {
            uint32_t qhf[4];
            ldsm_x4(qhf, sb + qrow * 144 + (kc * 16 + qkoff) * 2);
            #pragma unroll
            for (int ni = 0; ni < 8; ++ni) {
                uint32_t bb[4];   // [0..1]=K_hi, [2..3]=K_lo
                const uint32_t bo = st + losel + (ni * 8 + brow) * 144 + (kc * 16 + bkoff) * 2;
                ldsm_x4(bb, bo);
                mma_f32(s[ni], qhf, bb);
                mma_f32(s[ni], qhf, bb + 2);
            }
        }

        // mask
        #pragma unroll
        for (int ni = 0; ni < 8; ++ni) {
            if (msk[t * 64 + ni * 8 + c0] == 0)     { s[ni][0] = -1e9f; s[ni][2] = -1e9f; }
            if (msk[t * 64 + ni * 8 + c0 + 1] == 0) { s[ni][1] = -1e9f; s[ni][3] = -1e9f; }
        }

        // online softmax (2 rows per lane)
        #pragma unroll
        for (int rr = 0; rr < 2; ++rr) {
            float mx = -1e30f;
            #pragma unroll
            for (int ni = 0; ni < 8; ++ni)
                mx = fmaxf(mx, fmaxf(s[ni][rr * 2], s[ni][rr * 2 + 1]));
            mx = fmaxf(mx, __shfl_xor_sync(0xffffffffu, mx, 1));
            mx = fmaxf(mx, __shfl_xor_sync(0xffffffffu, mx, 2));
            const float nm = fmaxf(mst[rr], mx);
            const float corr = __expf(mst[rr] - nm);
            float sum = 0.0f;
            #pragma unroll
            for (int ni = 0; ni < 8; ++ni) {
                const float p0 = __expf(s[ni][rr * 2]     - nm);
                const float p1 = __expf(s[ni][rr * 2 + 1] - nm);
                s[ni][rr * 2] = p0; s[ni][rr * 2 + 1] = p1;
                sum += p0 + p1;
            }
            sum += __shfl_xor_sync(0xffffffffu, sum, 1);
            sum += __shfl_xor_sync(0xffffffffu, sum, 2);
            lst[rr] = lst[rr] * corr + sum;
            mst[rr] = nm;
            #pragma unroll
            for (int vi = 0; vi < 8; ++vi) {
                o[vi][rr * 2]     *= corr;
                o[vi][rr * 2 + 1] *= corr;
            }
        }

        // O += P @ (V_hi + V_lo)   (P plain fp16)
        #pragma unroll
        for (int kc = 0; kc < 4; ++kc) {
            uint32_t ph[4];
            ph[0] = h2pack(s[2 * kc][0],     s[2 * kc][1]);
            ph[1] = h2pack(s[2 * kc][2],     s[2 * kc][3]);
            ph[2] = h2pack(s[2 * kc + 1][0], s[2 * kc + 1][1]);
            ph[3] = h2pack(s[2 * kc + 1][2], s[2 * kc + 1][3]);
            #pragma unroll
            for (int vi = 0; vi < 8; ++vi) {
                uint32_t vv[4];   // [0..1]=V_hi, [2..3]=V_lo
                const uint32_t vo = st + F_VH + losel + (kc * 16 + vrow) * 144 + vi * 16;
                ldsm_x4t(vv, vo);
                mma_f32(o[vi], ph, vv);
                mma_f32(o[vi], ph, vv + 2);
            }
        }

        __syncthreads();
        if (t + 2 < 32) {
            kv_stage_issue(sb + F_ST0 + (uint32_t)(t & 1) * F_STAGE, Kh, Kl, Vh, Vl, t + 2, tid);
            CP_COMMIT();
        }
    }

    // epilogue: ctx hi only (A side of O proj), flat [b*S+s][D] at col h*64+dk
    #pragma unroll
    for (int rr = 0; rr < 2; ++rr) {
        const float inv = 1.0f / lst[rr];
        const int r = q0 + w * 16 + (lane >> 2) + rr * 8;
        const size_t base = ((size_t)b * S_N + r) * D_N + h * DK_N;
        #pragma unroll
        for (int vi = 0; vi < 8; ++vi) {
            const int dk = vi * 8 + c0;
            *(uint32_t*)(g_ch + base + dk) =
                h2pack(o[vi][rr * 2] * inv, o[vi][rr * 2 + 1] * inv);
        }
    }
}

// ---------------------------------------------------------------------------
extern "C" void kernel_launch(void* const* d_in, const int* in_sizes, int n_in,
                              void* d_out, int out_size)
{
    (void)in_sizes; (void)n_in; (void)out_size;
    const float* query = (const float*)d_in[0];
    const float* key   = (const float*)d_in[1];
    const float* value = (const float*)d_in[2];
    const int*   mask  = (const int*)d_in[3];
    const float* bq = (const float*)d_in[5];
    const float* bk = (const float*)d_in[7];
    const float* bv = (const float*)d_in[9];
    const float* bo = (const float*)d_in[11];
    const float* Wq = (const float*)d_in[4];
    const float* Wk = (const float*)d_in[6];
    const float* Wv = (const float*)d_in[8];
    const float* Wo = (const float*)d_in[10];
    float* out = (float*)d_out;

    cudaFuncSetAttribute(qkv_proj_mma, cudaFuncAttributeMaxDynamicSharedMemorySize, SMEM_GEMM);
    cudaFuncSetAttribute(oproj_mma,    cudaFuncAttributeMaxDynamicSharedMemorySize, SMEM_GEMM);
    cudaFuncSetAttribute(flash_mma,    cudaFuncAttributeMaxDynamicSharedMemorySize, SMEM_FLASH);

    convert_in<<<dim3(HEAD_EL / 4 / 256, 1, 3), 256>>>(query, key, value);
    convert_w<<<dim3(1024 * 1024 / 4 / 256, 1, 4), 256>>>(Wq, Wk, Wv, Wo);

    // GEMM grid: N tiles (1024/128=8) x M tiles (8192/128=64) [x3 for qkv]
    qkv_proj_mma<<<dim3(8, 64, 3), 256, SMEM_GEMM>>>(bq, bk, bv);

    // Flash grid: q-blocks (2048/256=8) x (b,h)=64
    flash_mma<<<dim3(8, B_N * H_N), 512, SMEM_FLASH>>>(mask);

    oproj_mma<<<dim3(8, 64), 256, SMEM_GEMM>>>(bo, out);
}

// round 11
// speedup vs baseline: 2.4505x; 1.6561x over previous
#include <cuda_runtime.h>
#include <cuda_fp16.h>
#include <stdint.h>

// Problem constants
#define B_N 4
#define S_N 2048
#define D_N 1024
#define H_N 16
#define DK_N 64

#define HEAD_EL (8192u * 1024u)        // B*H*S*DK == M*D
#define IN_EL   (3u * HEAD_EL)
#define W_EL    (4u * 1024u * 1024u)

// fp16 scratch (allocation-free) — single-term everywhere
__device__ __half g_inh[IN_EL];                  // q,k,v inputs
__device__ __half g_wh[W_EL];                    // weights
__device__ __half g_qh[HEAD_EL];                 // Q (pre-scaled 1/8)
__device__ __half g_kh[HEAD_EL];                 // K
__device__ __half g_vh[HEAD_EL];                 // V
__device__ __half g_ch[HEAD_EL];                 // ctx

// ===========================================================================
// Helpers (compute_103-portable: ldmatrix / mma.sync / cp.async)
// ===========================================================================
__device__ __forceinline__ uint32_t smem_u32(const void* p) {
    uint32_t a;
    asm("{ .reg .u64 t; cvta.to.shared.u64 t, %1; cvt.u32.u64 %0, t; }"
        : "=r"(a) : "l"(p));
    return a;
}
__device__ __forceinline__ void ldsm_x4(uint32_t* r, uint32_t addr) {
    asm volatile("ldmatrix.sync.aligned.m8n8.x4.shared.b16 {%0,%1,%2,%3}, [%4];"
        : "=r"(r[0]), "=r"(r[1]), "=r"(r[2]), "=r"(r[3]) : "r"(addr));
}
__device__ __forceinline__ void ldsm_x4t(uint32_t* r, uint32_t addr) {
    asm volatile("ldmatrix.sync.aligned.m8n8.x4.trans.shared.b16 {%0,%1,%2,%3}, [%4];"
        : "=r"(r[0]), "=r"(r[1]), "=r"(r[2]), "=r"(r[3]) : "r"(addr));
}
__device__ __forceinline__ void mma_f32(float* d, const uint32_t* a, const uint32_t* b) {
    asm volatile(
        "mma.sync.aligned.m16n8k16.row.col.f32.f16.f16.f32 "
        "{%0,%1,%2,%3}, {%4,%5,%6,%7}, {%8,%9}, {%0,%1,%2,%3};"
        : "+f"(d[0]), "+f"(d[1]), "+f"(d[2]), "+f"(d[3])
        : "r"(a[0]), "r"(a[1]), "r"(a[2]), "r"(a[3]), "r"(b[0]), "r"(b[1]));
}
__device__ __forceinline__ uint32_t h2pack(float x, float y) {
    union { __half2 h; uint32_t u; } t;
    t.h = __floats2half2_rn(x, y);
    return t.u;
}
__device__ __forceinline__ void cpa16(uint32_t s, const void* g) {
    asm volatile("cp.async.cg.shared.global [%0], [%1], 16;" :: "r"(s), "l"(g));
}
#define CP_COMMIT() asm volatile("cp.async.commit_group;" ::: "memory")
#define CP_WAIT(n)  asm volatile("cp.async.wait_group %0;" :: "n"(n) : "memory")

// ===========================================================================
// Pre-pass conversions (fp32 -> fp16)
// ===========================================================================
__global__ __launch_bounds__(256) void convert_in(
    const float* __restrict__ q, const float* __restrict__ k,
    const float* __restrict__ v)
{
    const int z = blockIdx.z;
    const float* src = (z == 0) ? q : (z == 1) ? k : v;
    __half* dh = g_inh + (size_t)z * HEAD_EL;
    const int i = blockIdx.x * 256 + threadIdx.x;
    const float4 val = ((const float4*)src)[i];
    ((uint2*)dh)[i] = make_uint2(h2pack(val.x, val.y), h2pack(val.z, val.w));
}

__global__ __launch_bounds__(256) void convert_w(
    const float* __restrict__ wq, const float* __restrict__ wk,
    const float* __restrict__ wv, const float* __restrict__ wo)
{
    const int z = blockIdx.z;
    const float* src = (z == 0) ? wq : (z == 1) ? wk : (z == 2) ? wv : wo;
    __half* dh = g_wh + (size_t)z * 1024 * 1024;
    const int i = blockIdx.x * 256 + threadIdx.x;
    const float4 val = ((const float4*)src)[i];
    ((uint2*)dh)[i] = make_uint2(h2pack(val.x, val.y), h2pack(val.z, val.w));
}

// ===========================================================================
// GEMM: D = A @ W^T (+bias). CTA 128x128, BK=32, 256 thr (8 warps, 32x64),
// single-term fp16, fp32 acc. 3-stage cp.async pipeline.
// Stage: A(10240) | B(10240) = 20480 B. Row stride 80 B.
// One ldmatrix.x4 feeds TWO n-tiles (lane bit4 -> +8 B rows).
// ===========================================================================
#define G_BH 10240
#define G_STAGE 20480
#define SMEM_GEMM (3 * G_STAGE) // 61440

__device__ __forceinline__ void gemm_stage_issue(
    uint32_t st, const __half* __restrict__ Ah,
    const __half* __restrict__ Wh, int kt, int tid)
{
    #pragma unroll
    for (int i = 0; i < 2; ++i) {
        const int c = tid + i * 256;             // 0..511
        const int row = c >> 2, ch = c & 3;
        const size_t s = (size_t)row * 1024 + kt * 32 + ch * 8;
        const uint32_t d = st + row * 80 + ch * 16;
        cpa16(d, Ah + s);                         // A
        cpa16(d + G_BH, Wh + s);                  // B
    }
}

template <int MODE>
__device__ __forceinline__ void gemm_h_body(
    const __half* __restrict__ Ah, const __half* __restrict__ Wh,
    const float* __restrict__ bias, float scale,
    float* __restrict__ outf, __half* __restrict__ outh,
    int bm, int bn)
{
    extern __shared__ char smg[];
    const uint32_t sb = smem_u32(smg);
    const int tid = threadIdx.x;
    const int lane = tid & 31;
    const int w = tid >> 5;
    const int wm = w & 3;               // rows wm*32
    const int wn = w >> 2;              // cols wn*64

    const __half* Agh = Ah + (size_t)bm * 128 * 1024;
    const __half* Wgh = Wh + (size_t)bn * 128 * 1024;

    gemm_stage_issue(sb,               Agh, Wgh, 0, tid); CP_COMMIT();
    gemm_stage_issue(sb + G_STAGE,     Agh, Wgh, 1, tid); CP_COMMIT();
    gemm_stage_issue(sb + 2 * G_STAGE, Agh, Wgh, 2, tid); CP_COMMIT();

    float d[2][8][4];
    #pragma unroll
    for (int mi = 0; mi < 2; ++mi)
        #pragma unroll
        for (int ni = 0; ni < 8; ++ni)
            #pragma unroll
            for (int q = 0; q < 4; ++q) d[mi][ni][q] = 0.0f;

    const int arow = wm * 32 + (lane & 15);
    const int akoff = (lane >> 4) << 3;
    // B-frag addressing: bit3 -> k+8, bit4 -> second n-tile (+8 rows)
    const int brow = wn * 64 + (lane & 7) + ((lane & 16) >> 1);
    const int bkoff = ((lane >> 3) & 1) << 3;

    for (int kt = 0; kt < 32; ++kt) {
        if (kt < 30) { CP_WAIT(2); } else if (kt == 30) { CP_WAIT(1); } else { CP_WAIT(0); }
        __syncthreads();
        const uint32_t st = sb + (uint32_t)(kt % 3) * G_STAGE;
        #pragma unroll
        for (int kk = 0; kk < 32; kk += 16) {
            uint32_t ah[2][4];
            #pragma unroll
            for (int mi = 0; mi < 2; ++mi)
                ldsm_x4(ah[mi], st + (arow + mi * 16) * 80 + (kk + akoff) * 2);
            #pragma unroll
            for (int ni = 0; ni < 8; ni += 2) {
                uint32_t bb[4];   // [0..1] = tile ni, [2..3] = tile ni+1
                ldsm_x4(bb, st + G_BH + (brow + ni * 8) * 80 + (kk + bkoff) * 2);
                #pragma unroll
                for (int mi = 0; mi < 2; ++mi) {
                    mma_f32(d[mi][ni],     ah[mi], bb);
                    mma_f32(d[mi][ni + 1], ah[mi], bb + 2);
                }
            }
        }
        __syncthreads();
        if (kt + 3 < 32) {
            gemm_stage_issue(sb + (uint32_t)(kt % 3) * G_STAGE, Agh, Wgh, kt + 3, tid);
            CP_COMMIT();
        }
    }

    // epilogue
    const int r_base = bm * 128 + wm * 32 + (lane >> 2);
    const int c_base = bn * 128 + wn * 64 + 2 * (lane & 3);
    #pragma unroll
    for (int mi = 0; mi < 2; ++mi)
        #pragma unroll
        for (int ni = 0; ni < 8; ++ni) {
            const int col = c_base + ni * 8;
            const float b0 = bias[col], b1 = bias[col + 1];
            #pragma unroll
            for (int rr = 0; rr < 2; ++rr) {
                const int row = r_base + mi * 16 + rr * 8;
                const float vx = (d[mi][ni][rr * 2 + 0] + b0) * scale;
                const float vy = (d[mi][ni][rr * 2 + 1] + b1) * scale;
                if (MODE == 1) {
                    const int bb = row >> 11;
                    const int s = row & (S_N - 1);
                    const int hh = col >> 6;
                    const int dk = col & 63;
                    const size_t idx = (((size_t)(bb * H_N + hh) * S_N + s) * DK_N) + dk;
                    *(uint32_t*)(outh + idx) = h2pack(vx, vy);
                } else {
                    float2 v; v.x = vx; v.y = vy;
                    *(float2*)(outf + (size_t)row * D_N + col) = v;
                }
            }
        }
}

__global__ __launch_bounds__(256) void qkv_proj_mma(
    const float* __restrict__ bq, const float* __restrict__ bk,
    const float* __restrict__ bv)
{
    const int z = blockIdx.z;
    const float* bias = (z == 0) ? bq : (z == 1) ? bk : bv;
    __half* oh = (z == 0) ? g_qh : (z == 1) ? g_kh : g_vh;
    const float scale = (z == 0) ? 0.125f : 1.0f;
    gemm_h_body<1>(g_inh + (size_t)z * HEAD_EL,
                   g_wh + (size_t)z * 1024 * 1024,
                   bias, scale, nullptr, oh, blockIdx.y, blockIdx.x);
}

__global__ __launch_bounds__(256) void oproj_mma(
    const float* __restrict__ bo, float* __restrict__ out)
{
    gemm_h_body<0>(g_ch, g_wh + (size_t)3 * 1024 * 1024,
                   bo, 1.0f, out, nullptr, blockIdx.y, blockIdx.x);
}

// ===========================================================================
// Flash attention: CTA = one (b,h) x 256 q-rows, 512 thr (16 warps x 16 rows),
// 64-key tiles, 2-stage cp.async KV pipeline, online softmax, pure fp16.
// Q persistent in smem (256 x 144 B). Stage: K(9216) | V(9216).
// One ldmatrix.x4 / .x4t feeds TWO n- / dk-tiles via lane bit4.
// ===========================================================================
#define F_ST0 36864              // Q = 256*144
#define F_VH 9216                // V offset within stage
#define F_STAGE 18432
#define F_MS (F_ST0 + 2 * F_STAGE)     // 73728
#define SMEM_FLASH (F_MS + 8192)       // 81920

__device__ __forceinline__ void kv_stage_issue(
    uint32_t st, const __half* __restrict__ kh, const __half* __restrict__ vh,
    int t, int tid)
{
    const int c = tid & 511;                // 0..511
    const int row = c >> 3, ch = c & 7;
    const size_t s = ((size_t)t * 64 + row) * 64 + ch * 8;
    const uint32_t d = st + row * 144 + ch * 16;
    cpa16(d, kh + s);
    cpa16(d + F_VH, vh + s);
}

__global__ __launch_bounds__(512, 1)
void flash_mma(const int* __restrict__ mask)
{
    extern __shared__ char smf[];
    const uint32_t sb = smem_u32(smf);
    const int tid = threadIdx.x;
    const int lane = tid & 31;
    const int w = tid >> 5;
    const int bh = blockIdx.y;
    const int q0 = blockIdx.x * 256;
    const int b = bh >> 4;
    const int h = bh & 15;

    const size_t hoff = (size_t)bh * S_N * DK_N;
    const __half* Qh = g_qh + hoff + (size_t)q0 * DK_N;
    const __half* Kh = g_kh + hoff;
    const __half* Vh = g_vh + hoff;
    const int* mg = mask + b * S_N;

    // prologue: Q + mask (group 0), KV stages 0,1 (groups 1,2)
    #pragma unroll
    for (int i = 0; i < 4; ++i) {
        const int c = tid + i * 512;            // 0..2047
        const int row = c >> 3, ch = c & 7;
        cpa16(sb + row * 144 + ch * 16, Qh + (size_t)row * 64 + ch * 8);
    }
    cpa16(sb + F_MS + tid * 16, mg + tid * 4);  // 8192 B
    CP_COMMIT();
    kv_stage_issue(sb + F_ST0,           Kh, Vh, 0, tid); CP_COMMIT();
    kv_stage_issue(sb + F_ST0 + F_STAGE, Kh, Vh, 1, tid); CP_COMMIT();

    float o[8][4];
    #pragma unroll
    for (int vi = 0; vi < 8; ++vi)
        #pragma unroll
        for (int q = 0; q < 4; ++q) o[vi][q] = 0.0f;
    float mst[2] = {-1e30f, -1e30f};
    float lst[2] = {0.0f, 0.0f};

    const int qrow = w * 16 + (lane & 15);
    const int qkoff = (lane >> 4) << 3;
    // K-frag: bit3 -> k+8, bit4 -> second key-tile (+8 rows)
    const int brow = (lane & 7) + ((lane & 16) >> 1);
    const int bkoff = ((lane >> 3) & 1) << 3;
    // V-frag (trans): bit3 -> +8 k-rows, bit4 -> second dk-tile (+16 B cols)
    const int vrow = (lane & 7) + (((lane >> 3) & 1) << 3);
    const uint32_t vcoff = (lane & 16) ? 16u : 0u;
    const int c0 = 2 * (lane & 3);
    const int* msk = (const int*)(smf + F_MS);

    for (int t = 0; t < 32; ++t) {
        if (t < 31) { CP_WAIT(1); } else { CP_WAIT(0); }
        __syncthreads();
        const uint32_t st = sb + F_ST0 + (uint32_t)(t & 1) * F_STAGE;

        // S = Q @ K^T  (16 rows x 64 keys per warp)
        float s[8][4];
        #pragma unroll
        for (int ni = 0; ni < 8; ++ni)
            s[ni][0] = s[ni][1] = s[ni][2] = s[ni][3] = 0.0f;

        #pragma unroll
        for (int kc = 0; kc < 4; ++kc) {
            uint32_t qhf[4];
            ldsm_x4(qhf, sb + qrow * 144 + (kc * 16 + qkoff) * 2);
            #pragma unroll
            for (int ni = 0; ni < 8; ni += 2) {
                uint32_t bb[4];   // [0..1]=tile ni, [2..3]=tile ni+1
                ldsm_x4(bb, st + (ni * 8 + brow) * 144 + (kc * 16 + bkoff) * 2);
                mma_f32(s[ni],     qhf, bb);
                mma_f32(s[ni + 1], qhf, bb + 2);
            }
        }

        // mask
        #pragma unroll
        for (int ni = 0; ni < 8; ++ni) {
            if (msk[t * 64 + ni * 8 + c0] == 0)     { s[ni][0] = -1e9f; s[ni][2] = -1e9f; }
            if (msk[t * 64 + ni * 8 + c0 + 1] == 0) { s[ni][1] = -1e9f; s[ni][3] = -1e9f; }
        }

        // online softmax (2 rows per lane)
        #pragma unroll
        for (int rr = 0; rr < 2; ++rr) {
            float mx = -1e30f;
            #pragma unroll
            for (int ni = 0; ni < 8; ++ni)
                mx = fmaxf(mx, fmaxf(s[ni][rr * 2], s[ni][rr * 2 + 1]));
            mx = fmaxf(mx, __shfl_xor_sync(0xffffffffu, mx, 1));
            mx = fmaxf(mx, __shfl_xor_sync(0xffffffffu, mx, 2));
            const float nm = fmaxf(mst[rr], mx);
            const float corr = __expf(mst[rr] - nm);
            float sum = 0.0f;
            #pragma unroll
            for (int ni = 0; ni < 8; ++ni) {
                const float p0 = __expf(s[ni][rr * 2]     - nm);
                const float p1 = __expf(s[ni][rr * 2 + 1] - nm);
                s[ni][rr * 2] = p0; s[ni][rr * 2 + 1] = p1;
                sum += p0 + p1;
            }
            sum += __shfl_xor_sync(0xffffffffu, sum, 1);
            sum += __shfl_xor_sync(0xffffffffu, sum, 2);
            lst[rr] = lst[rr] * corr + sum;
            mst[rr] = nm;
            #pragma unroll
            for (int vi = 0; vi < 8; ++vi) {
                o[vi][rr * 2]     *= corr;
                o[vi][rr * 2 + 1] *= corr;
            }
        }

        // O += P @ V   (P plain fp16)
        #pragma unroll
        for (int kc = 0; kc < 4; ++kc) {
            uint32_t ph[4];
            ph[0] = h2pack(s[2 * kc][0],     s[2 * kc][1]);
            ph[1] = h2pack(s[2 * kc][2],     s[2 * kc][3]);
            ph[2] = h2pack(s[2 * kc + 1][0], s[2 * kc + 1][1]);
            ph[3] = h2pack(s[2 * kc + 1][2], s[2 * kc + 1][3]);
            #pragma unroll
            for (int vi = 0; vi < 8; vi += 2) {
                uint32_t vv[4];   // [0..1]=dk tile vi, [2..3]=dk tile vi+1
                ldsm_x4t(vv, st + F_VH + (kc * 16 + vrow) * 144 + vi * 16 + vcoff);
                mma_f32(o[vi],     ph, vv);
                mma_f32(o[vi + 1], ph, vv + 2);
            }
        }

        __syncthreads();
        if (t + 2 < 32) {
            kv_stage_issue(sb + F_ST0 + (uint32_t)(t & 1) * F_STAGE, Kh, Vh, t + 2, tid);
            CP_COMMIT();
        }
    }

    // epilogue: ctx fp16, flat [b*S+s][D] at col h*64+dk
    #pragma unroll
    for (int rr = 0; rr < 2; ++rr) {
        const float inv = 1.0f / lst[rr];
        const int r = q0 + w * 16 + (lane >> 2) + rr * 8;
        const size_t base = ((size_t)b * S_N + r) * D_N + h * DK_N;
        #pragma unroll
        for (int vi = 0; vi < 8; ++vi) {
            const int dk = vi * 8 + c0;
            *(uint32_t*)(g_ch + base + dk) =
                h2pack(o[vi][rr * 2] * inv, o[vi][rr * 2 + 1] * inv);
        }
    }
}

// ---------------------------------------------------------------------------
extern "C" void kernel_launch(void* const* d_in, const int* in_sizes, int n_in,
                              void* d_out, int out_size)
{
    (void)in_sizes; (void)n_in; (void)out_size;
    const float* query = (const float*)d_in[0];
    const float* key   = (const float*)d_in[1];
    const float* value = (const float*)d_in[2];
    const int*   mask  = (const int*)d_in[3];
    const float* Wq = (const float*)d_in[4];
    const float* bq = (const float*)d_in[5];
    const float* Wk = (const float*)d_in[6];
    const float* bk = (const float*)d_in[7];
    const float* Wv = (const float*)d_in[8];
    const float* bv = (const float*)d_in[9];
    const float* Wo = (const float*)d_in[10];
    const float* bo = (const float*)d_in[11];
    float* out = (float*)d_out;

    cudaFuncSetAttribute(qkv_proj_mma, cudaFuncAttributeMaxDynamicSharedMemorySize, SMEM_GEMM);
    cudaFuncSetAttribute(oproj_mma,    cudaFuncAttributeMaxDynamicSharedMemorySize, SMEM_GEMM);
    cudaFuncSetAttribute(flash_mma,    cudaFuncAttributeMaxDynamicSharedMemorySize, SMEM_FLASH);

    convert_in<<<dim3(HEAD_EL / 4 / 256, 1, 3), 256>>>(query, key, value);
    convert_w<<<dim3(1024 * 1024 / 4 / 256, 1, 4), 256>>>(Wq, Wk, Wv, Wo);

    // GEMM grid: N tiles (1024/128=8) x M tiles (8192/128=64) [x3 for qkv]
    qkv_proj_mma<<<dim3(8, 64, 3), 256, SMEM_GEMM>>>(bq, bk, bv);

    // Flash grid: q-blocks (2048/256=8) x (b,h)=64
    flash_mma<<<dim3(8, B_N * H_N), 512, SMEM_FLASH>>>(mask);

    oproj_mma<<<dim3(8, 64), 256, SMEM_GEMM>>>(bo, out);
}

// round 12
// speedup vs baseline: 2.6086x; 1.0645x over previous
#include <cuda_runtime.h>
#include <cuda_fp16.h>
#include <stdint.h>

// Problem constants
#define B_N 4
#define S_N 2048
#define D_N 1024
#define H_N 16
#define DK_N 64

#define HEAD_EL (8192u * 1024u)        // B*H*S*DK == M*D
#define IN_EL   (3u * HEAD_EL)
#define W_EL    (4u * 1024u * 1024u)

// fp16 scratch (allocation-free) — single-term everywhere
__device__ __half g_inh[IN_EL];                  // q,k,v inputs
__device__ __half g_wh[W_EL];                    // weights
__device__ __half g_qh[HEAD_EL];                 // Q (pre-scaled 0.125*log2e)
__device__ __half g_kh[HEAD_EL];                 // K
__device__ __half g_vh[HEAD_EL];                 // V
__device__ __half g_ch[HEAD_EL];                 // ctx

// ===========================================================================
// Helpers (compute_103-portable: ldmatrix / mma.sync / cp.async)
// ===========================================================================
__device__ __forceinline__ uint32_t smem_u32(const void* p) {
    uint32_t a;
    asm("{ .reg .u64 t; cvta.to.shared.u64 t, %1; cvt.u32.u64 %0, t; }"
        : "=r"(a) : "l"(p));
    return a;
}
__device__ __forceinline__ void ldsm_x4(uint32_t* r, uint32_t addr) {
    asm volatile("ldmatrix.sync.aligned.m8n8.x4.shared.b16 {%0,%1,%2,%3}, [%4];"
        : "=r"(r[0]), "=r"(r[1]), "=r"(r[2]), "=r"(r[3]) : "r"(addr));
}
__device__ __forceinline__ void ldsm_x4t(uint32_t* r, uint32_t addr) {
    asm volatile("ldmatrix.sync.aligned.m8n8.x4.trans.shared.b16 {%0,%1,%2,%3}, [%4];"
        : "=r"(r[0]), "=r"(r[1]), "=r"(r[2]), "=r"(r[3]) : "r"(addr));
}
__device__ __forceinline__ void mma_f32(float* d, const uint32_t* a, const uint32_t* b) {
    asm volatile(
        "mma.sync.aligned.m16n8k16.row.col.f32.f16.f16.f32 "
        "{%0,%1,%2,%3}, {%4,%5,%6,%7}, {%8,%9}, {%0,%1,%2,%3};"
        : "+f"(d[0]), "+f"(d[1]), "+f"(d[2]), "+f"(d[3])
        : "r"(a[0]), "r"(a[1]), "r"(a[2]), "r"(a[3]), "r"(b[0]), "r"(b[1]));
}
__device__ __forceinline__ uint32_t h2pack(float x, float y) {
    union { __half2 h; uint32_t u; } t;
    t.h = __floats2half2_rn(x, y);
    return t.u;
}
__device__ __forceinline__ float ex2(float x) {
    float y;
    asm("ex2.approx.f32 %0, %1;" : "=f"(y) : "f"(x));
    return y;
}
__device__ __forceinline__ void cpa16(uint32_t s, const void* g) {
    asm volatile("cp.async.cg.shared.global [%0], [%1], 16;" :: "r"(s), "l"(g));
}
#define CP_COMMIT() asm volatile("cp.async.commit_group;" ::: "memory")
#define CP_WAIT(n)  asm volatile("cp.async.wait_group %0;" :: "n"(n) : "memory")

// ===========================================================================
// Pre-pass conversions (fp32 -> fp16)
// ===========================================================================
__global__ __launch_bounds__(256) void convert_in(
    const float* __restrict__ q, const float* __restrict__ k,
    const float* __restrict__ v)
{
    const int z = blockIdx.z;
    const float* src = (z == 0) ? q : (z == 1) ? k : v;
    __half* dh = g_inh + (size_t)z * HEAD_EL;
    const int i = blockIdx.x * 256 + threadIdx.x;
    const float4 val = ((const float4*)src)[i];
    ((uint2*)dh)[i] = make_uint2(h2pack(val.x, val.y), h2pack(val.z, val.w));
}

__global__ __launch_bounds__(256) void convert_w(
    const float* __restrict__ wq, const float* __restrict__ wk,
    const float* __restrict__ wv, const float* __restrict__ wo)
{
    const int z = blockIdx.z;
    const float* src = (z == 0) ? wq : (z == 1) ? wk : (z == 2) ? wv : wo;
    __half* dh = g_wh + (size_t)z * 1024 * 1024;
    const int i = blockIdx.x * 256 + threadIdx.x;
    const float4 val = ((const float4*)src)[i];
    ((uint2*)dh)[i] = make_uint2(h2pack(val.x, val.y), h2pack(val.z, val.w));
}

// ===========================================================================
// GEMM: D = A @ W^T (+bias). CTA 128x128, BK=32, 256 thr (8 warps, 32x64),
// single-term fp16, fp32 acc. 3-stage cp.async pipeline, ONE sync/iter
// (prefetch issued post-sync into the slot freed last iteration).
// Stage: A(10240) | B(10240) = 20480 B. Row stride 80 B.
// ===========================================================================
#define G_BH 10240
#define G_STAGE 20480
#define SMEM_GEMM (3 * G_STAGE) // 61440

__device__ __forceinline__ void gemm_stage_issue(
    uint32_t st, const __half* __restrict__ Ah,
    const __half* __restrict__ Wh, int kt, int tid)
{
    #pragma unroll
    for (int i = 0; i < 2; ++i) {
        const int c = tid + i * 256;             // 0..511
        const int row = c >> 2, ch = c & 3;
        const size_t s = (size_t)row * 1024 + kt * 32 + ch * 8;
        const uint32_t d = st + row * 80 + ch * 16;
        cpa16(d, Ah + s);                         // A
        cpa16(d + G_BH, Wh + s);                  // B
    }
}

template <int MODE>
__device__ __forceinline__ void gemm_h_body(
    const __half* __restrict__ Ah, const __half* __restrict__ Wh,
    const float* __restrict__ bias, float scale,
    float* __restrict__ outf, __half* __restrict__ outh,
    int bm, int bn)
{
    extern __shared__ char smg[];
    const uint32_t sb = smem_u32(smg);
    const int tid = threadIdx.x;
    const int lane = tid & 31;
    const int w = tid >> 5;
    const int wm = w & 3;               // rows wm*32
    const int wn = w >> 2;              // cols wn*64

    const __half* Agh = Ah + (size_t)bm * 128 * 1024;
    const __half* Wgh = Wh + (size_t)bn * 128 * 1024;

    gemm_stage_issue(sb,           Agh, Wgh, 0, tid); CP_COMMIT();
    gemm_stage_issue(sb + G_STAGE, Agh, Wgh, 1, tid); CP_COMMIT();

    float d[2][8][4];
    #pragma unroll
    for (int mi = 0; mi < 2; ++mi)
        #pragma unroll
        for (int ni = 0; ni < 8; ++ni)
            #pragma unroll
            for (int q = 0; q < 4; ++q) d[mi][ni][q] = 0.0f;

    const int arow = wm * 32 + (lane & 15);
    const int akoff = (lane >> 4) << 3;
    // B-frag addressing: bit3 -> k+8, bit4 -> second n-tile (+8 B rows)
    const int brow = wn * 64 + (lane & 7) + ((lane & 16) >> 1);
    const int bkoff = ((lane >> 3) & 1) << 3;

    for (int kt = 0; kt < 32; ++kt) {
        if (kt < 31) { CP_WAIT(1); } else { CP_WAIT(0); }
        __syncthreads();
        if (kt + 2 < 32) {   // slot (kt+2)%3 == (kt-1)%3, freed by the barrier
            gemm_stage_issue(sb + (uint32_t)((kt + 2) % 3) * G_STAGE, Agh, Wgh, kt + 2, tid);
            CP_COMMIT();
        }
        const uint32_t st = sb + (uint32_t)(kt % 3) * G_STAGE;
        #pragma unroll
        for (int kk = 0; kk < 32; kk += 16) {
            uint32_t ah[2][4];
            #pragma unroll
            for (int mi = 0; mi < 2; ++mi)
                ldsm_x4(ah[mi], st + (arow + mi * 16) * 80 + (kk + akoff) * 2);
            #pragma unroll
            for (int ni = 0; ni < 8; ni += 2) {
                uint32_t bb[4];   // [0..1] = tile ni, [2..3] = tile ni+1
                ldsm_x4(bb, st + G_BH + (brow + ni * 8) * 80 + (kk + bkoff) * 2);
                #pragma unroll
                for (int mi = 0; mi < 2; ++mi) {
                    mma_f32(d[mi][ni],     ah[mi], bb);
                    mma_f32(d[mi][ni + 1], ah[mi], bb + 2);
                }
            }
        }
    }

    // epilogue
    const int r_base = bm * 128 + wm * 32 + (lane >> 2);
    const int c_base = bn * 128 + wn * 64 + 2 * (lane & 3);
    #pragma unroll
    for (int mi = 0; mi < 2; ++mi)
        #pragma unroll
        for (int ni = 0; ni < 8; ++ni) {
            const int col = c_base + ni * 8;
            const float b0 = bias[col], b1 = bias[col + 1];
            #pragma unroll
            for (int rr = 0; rr < 2; ++rr) {
                const int row = r_base + mi * 16 + rr * 8;
                const float vx = (d[mi][ni][rr * 2 + 0] + b0) * scale;
                const float vy = (d[mi][ni][rr * 2 + 1] + b1) * scale;
                if (MODE == 1) {
                    const int bb = row >> 11;
                    const int s = row & (S_N - 1);
                    const int hh = col >> 6;
                    const int dk = col & 63;
                    const size_t idx = (((size_t)(bb * H_N + hh) * S_N + s) * DK_N) + dk;
                    *(uint32_t*)(outh + idx) = h2pack(vx, vy);
                } else {
                    float2 v; v.x = vx; v.y = vy;
                    *(float2*)(outf + (size_t)row * D_N + col) = v;
                }
            }
        }
}

__global__ __launch_bounds__(256) void qkv_proj_mma(
    const float* __restrict__ bq, const float* __restrict__ bk,
    const float* __restrict__ bv)
{
    const int z = blockIdx.z;
    const float* bias = (z == 0) ? bq : (z == 1) ? bk : bv;
    __half* oh = (z == 0) ? g_qh : (z == 1) ? g_kh : g_vh;
    // Q carries 1/8 * log2(e) so flash softmax runs in exp2 domain
    const float scale = (z == 0) ? 0.125f * 1.44269504f : 1.0f;
    gemm_h_body<1>(g_inh + (size_t)z * HEAD_EL,
                   g_wh + (size_t)z * 1024 * 1024,
                   bias, scale, nullptr, oh, blockIdx.y, blockIdx.x);
}

__global__ __launch_bounds__(256) void oproj_mma(
    const float* __restrict__ bo, float* __restrict__ out)
{
    gemm_h_body<0>(g_ch, g_wh + (size_t)3 * 1024 * 1024,
                   bo, 1.0f, out, nullptr, blockIdx.y, blockIdx.x);
}

// ===========================================================================
// Flash attention: CTA = one (b,h) x 256 q-rows, 512 thr (16 warps x 16 rows),
// 64-key tiles, 3-stage cp.async KV pipeline (ONE sync/iter), exp2-domain
// online softmax with per-lane partial row sums + all-ones mask fast path.
// Q persistent in smem (256 x 144 B). Stage: K(9216) | V(9216).
// ===========================================================================
#define F_ST0 36864              // Q = 256*144
#define F_VH 9216                // V offset within stage
#define F_STAGE 18432
#define F_MS (F_ST0 + 3 * F_STAGE)     // 92160
#define F_FLAGS (F_MS + 8192)          // 100352
#define SMEM_FLASH (F_FLAGS + 128)     // 100480

__device__ __forceinline__ void kv_stage_issue(
    uint32_t st, const __half* __restrict__ kh, const __half* __restrict__ vh,
    int t, int tid)
{
    const int c = tid & 511;                // 0..511
    const int row = c >> 3, ch = c & 7;
    const size_t s = ((size_t)t * 64 + row) * 64 + ch * 8;
    const uint32_t d = st + row * 144 + ch * 16;
    cpa16(d, kh + s);
    cpa16(d + F_VH, vh + s);
}

__global__ __launch_bounds__(512, 1)
void flash_mma(const int* __restrict__ mask)
{
    extern __shared__ char smf[];
    const uint32_t sb = smem_u32(smf);
    const int tid = threadIdx.x;
    const int lane = tid & 31;
    const int w = tid >> 5;
    const int bh = blockIdx.y;
    const int q0 = blockIdx.x * 256;
    const int b = bh >> 4;
    const int h = bh & 15;

    const size_t hoff = (size_t)bh * S_N * DK_N;
    const __half* Qh = g_qh + hoff + (size_t)q0 * DK_N;
    const __half* Kh = g_kh + hoff;
    const __half* Vh = g_vh + hoff;
    const int* mg = mask + b * S_N;

    // prologue: Q + mask (group 0), KV stages 0,1 (groups 1,2)
    #pragma unroll
    for (int i = 0; i < 4; ++i) {
        const int c = tid + i * 512;            // 0..2047
        const int row = c >> 3, ch = c & 7;
        cpa16(sb + row * 144 + ch * 16, Qh + (size_t)row * 64 + ch * 8);
    }
    cpa16(sb + F_MS + tid * 16, mg + tid * 4);  // 8192 B
    CP_COMMIT();
    kv_stage_issue(sb + F_ST0,           Kh, Vh, 0, tid); CP_COMMIT();
    kv_stage_issue(sb + F_ST0 + F_STAGE, Kh, Vh, 1, tid); CP_COMMIT();

    float o[8][4];
    #pragma unroll
    for (int vi = 0; vi < 8; ++vi)
        #pragma unroll
        for (int q = 0; q < 4; ++q) o[vi][q] = 0.0f;
    float mst[2] = {-1e30f, -1e30f};
    float lst[2] = {0.0f, 0.0f};     // per-lane partial sums (reduced at end)

    const int qrow = w * 16 + (lane & 15);
    const int qkoff = (lane >> 4) << 3;
    const int brow = (lane & 7) + ((lane & 16) >> 1);
    const int bkoff = ((lane >> 3) & 1) << 3;
    const int vrow = (lane & 7) + (((lane >> 3) & 1) << 3);
    const uint32_t vcoff = (lane & 16) ? 16u : 0u;
    const int c0 = 2 * (lane & 3);
    const int* msk = (const int*)(smf + F_MS);
    const int* flg = (const int*)(smf + F_FLAGS);

    for (int t = 0; t < 32; ++t) {
        if (t < 31) { CP_WAIT(1); } else { CP_WAIT(0); }
        __syncthreads();
        if (t + 2 < 32) {   // slot (t+2)%3 == (t-1)%3, freed by the barrier
            kv_stage_issue(sb + F_ST0 + (uint32_t)((t + 2) % 3) * F_STAGE, Kh, Vh, t + 2, tid);
            CP_COMMIT();
        }
        if (t == 0) {
            // per-tile mask flags: tile = 64 ints; warp w covers tiles 2w, 2w+1
            const int j = tid * 4;
            const bool ok = msk[j] && msk[j + 1] && msk[j + 2] && msk[j + 3];
            const unsigned bal = __ballot_sync(0xffffffffu, ok);
            if (lane == 0)  ((int*)(smf + F_FLAGS))[w * 2]     = ((bal & 0xffffu) == 0xffffu);
            if (lane == 16) ((int*)(smf + F_FLAGS))[w * 2 + 1] = ((bal >> 16) == 0xffffu);
            __syncthreads();
        }
        const uint32_t st = sb + F_ST0 + (uint32_t)(t % 3) * F_STAGE;

        // S = Q @ K^T  (16 rows x 64 keys per warp), log2 domain
        float s[8][4];
        #pragma unroll
        for (int ni = 0; ni < 8; ++ni)
            s[ni][0] = s[ni][1] = s[ni][2] = s[ni][3] = 0.0f;

        #pragma unroll
        for (int kc = 0; kc < 4; ++kc) {
            uint32_t qhf[4];
            ldsm_x4(qhf, sb + qrow * 144 + (kc * 16 + qkoff) * 2);
            #pragma unroll
            for (int ni = 0; ni < 8; ni += 2) {
                uint32_t bb[4];
                ldsm_x4(bb, st + (ni * 8 + brow) * 144 + (kc * 16 + bkoff) * 2);
                mma_f32(s[ni],     qhf, bb);
                mma_f32(s[ni + 1], qhf, bb + 2);
            }
        }

        // mask (skipped when the whole tile is nonzero)
        if (!flg[t]) {
            #pragma unroll
            for (int ni = 0; ni < 8; ++ni) {
                if (msk[t * 64 + ni * 8 + c0] == 0)     { s[ni][0] = -1e9f; s[ni][2] = -1e9f; }
                if (msk[t * 64 + ni * 8 + c0 + 1] == 0) { s[ni][1] = -1e9f; s[ni][3] = -1e9f; }
            }
        }

        // online softmax, exp2 domain (2 rows per lane)
        #pragma unroll
        for (int rr = 0; rr < 2; ++rr) {
            float mx = -1e30f;
            #pragma unroll
            for (int ni = 0; ni < 8; ++ni)
                mx = fmaxf(mx, fmaxf(s[ni][rr * 2], s[ni][rr * 2 + 1]));
            mx = fmaxf(mx, __shfl_xor_sync(0xffffffffu, mx, 1));
            mx = fmaxf(mx, __shfl_xor_sync(0xffffffffu, mx, 2));
            const float nm = fmaxf(mst[rr], mx);
            const float corr = ex2(mst[rr] - nm);
            float sum = 0.0f;
            #pragma unroll
            for (int ni = 0; ni < 8; ++ni) {
                const float p0 = ex2(s[ni][rr * 2]     - nm);
                const float p1 = ex2(s[ni][rr * 2 + 1] - nm);
                s[ni][rr * 2] = p0; s[ni][rr * 2 + 1] = p1;
                sum += p0 + p1;
            }
            lst[rr] = lst[rr] * corr + sum;   // per-lane partial
            mst[rr] = nm;
            #pragma unroll
            for (int vi = 0; vi < 8; ++vi) {
                o[vi][rr * 2]     *= corr;
                o[vi][rr * 2 + 1] *= corr;
            }
        }

        // O += P @ V   (P plain fp16)
        #pragma unroll
        for (int kc = 0; kc < 4; ++kc) {
            uint32_t ph[4];
            ph[0] = h2pack(s[2 * kc][0],     s[2 * kc][1]);
            ph[1] = h2pack(s[2 * kc][2],     s[2 * kc][3]);
            ph[2] = h2pack(s[2 * kc + 1][0], s[2 * kc + 1][1]);
            ph[3] = h2pack(s[2 * kc + 1][2], s[2 * kc + 1][3]);
            #pragma unroll
            for (int vi = 0; vi < 8; vi += 2) {
                uint32_t vv[4];
                ldsm_x4t(vv, st + F_VH + (kc * 16 + vrow) * 144 + vi * 16 + vcoff);
                mma_f32(o[vi],     ph, vv);
                mma_f32(o[vi + 1], ph, vv + 2);
            }
        }
    }

    // epilogue: reduce l across the 4 lanes of each row, write ctx fp16
    #pragma unroll
    for (int rr = 0; rr < 2; ++rr) {
        float ltot = lst[rr];
        ltot += __shfl_xor_sync(0xffffffffu, ltot, 1);
        ltot += __shfl_xor_sync(0xffffffffu, ltot, 2);
        const float inv = 1.0f / ltot;
        const int r = q0 + w * 16 + (lane >> 2) + rr * 8;
        const size_t base = ((size_t)b * S_N + r) * D_N + h * DK_N;
        #pragma unroll
        for (int vi = 0; vi < 8; ++vi) {
            const int dk = vi * 8 + c0;
            *(uint32_t*)(g_ch + base + dk) =
                h2pack(o[vi][rr * 2] * inv, o[vi][rr * 2 + 1] * inv);
        }
    }
}

// ---------------------------------------------------------------------------
extern "C" void kernel_launch(void* const* d_in, const int* in_sizes, int n_in,
                              void* d_out, int out_size)
{
    (void)in_sizes; (void)n_in; (void)out_size;
    const float* query = (const float*)d_in[0];
    const float* key   = (const float*)d_in[1];
    const float* value = (const float*)d_in[2];
    const int*   mask  = (const int*)d_in[3];
    const float* Wq = (const float*)d_in[4];
    const float* bq = (const float*)d_in[5];
    const float* Wk = (const float*)d_in[6];
    const float* bk = (const float*)d_in[7];
    const float* Wv = (const float*)d_in[8];
    const float* bv = (const float*)d_in[9];
    const float* Wo = (const float*)d_in[10];
    const float* bo = (const float*)d_in[11];
    float* out = (float*)d_out;

    cudaFuncSetAttribute(qkv_proj_mma, cudaFuncAttributeMaxDynamicSharedMemorySize, SMEM_GEMM);
    cudaFuncSetAttribute(oproj_mma,    cudaFuncAttributeMaxDynamicSharedMemorySize, SMEM_GEMM);
    cudaFuncSetAttribute(flash_mma,    cudaFuncAttributeMaxDynamicSharedMemorySize, SMEM_FLASH);

    convert_in<<<dim3(HEAD_EL / 4 / 256, 1, 3), 256>>>(query, key, value);
    convert_w<<<dim3(1024 * 1024 / 4 / 256, 1, 4), 256>>>(Wq, Wk, Wv, Wo);

    qkv_proj_mma<<<dim3(8, 64, 3), 256, SMEM_GEMM>>>(bq, bk, bv);

    flash_mma<<<dim3(8, B_N * H_N), 512, SMEM_FLASH>>>(mask);

    oproj_mma<<<dim3(8, 64), 256, SMEM_GEMM>>>(bo, out);
}